// round 5
// baseline (speedup 1.0000x reference)
#include <cuda_runtime.h>

// -----------------------------------------------------------------------------
// Round 5: R4 + occupancy 12 -> 16 warps/SM.
// Single-buffered K AND V (smem 70.6KB -> 53.2KB => 4 blocks/SM).
// cp.async schedule: V(t) issued at loop top (covered by S+softmax),
// K(t+1) issued post-S (covered by softmax+PV). 3 barriers/iter.
// -----------------------------------------------------------------------------

#define NT 128
#define QKSCALE (0.125f * 1.44269504088896f)

// units sorted by descending seqlen for tail packing
__constant__ int c_seqlen[8] = {1152, 1008, 864, 720, 640, 560, 480, 400};
__constant__ int c_batch[8]  = {1,    5,    3,   7,   0,   4,   2,   6};
__constant__ int c_soff[8]   = {512,  512,  512, 512, 0,   0,   0,   0};
__constant__ int c_obase[8]  = {2080, 4096, 3232, 5104, 0, 1120, 640, 1680};
__constant__ int c_qstart[8] = {0, 18, 34, 48, 60, 70, 79, 87};   // cum ceil(seq/64); total 94

#define QS_STRIDE 68
#define KS_STRIDE 68
#define VS_STRIDE 72
// smem float offsets (Q/P overlaid; K and V single-buffered)
#define SM_QP  0                                  // 64 x 68 (Q prologue, P mainloop)
#define SM_K   (64*QS_STRIDE)                     // 4352
#define SM_V   (SM_K + 64*KS_STRIDE)              // 8704
#define SM_TOTAL_FLOATS (SM_V + 64*VS_STRIDE)     // 13312 floats = 53248 B

__device__ __forceinline__ unsigned f2tf(float f) {
    unsigned u; asm("cvt.rna.tf32.f32 %0, %1;" : "=r"(u) : "f"(f)); return u;
}
__device__ __forceinline__ float ex2(float x) {
    float y; asm("ex2.approx.f32 %0, %1;" : "=f"(y) : "f"(x)); return y;
}
__device__ __forceinline__ void mma8(float d[4], const unsigned a[4], unsigned b0, unsigned b1) {
    asm volatile("mma.sync.aligned.m16n8k8.row.col.f32.tf32.tf32.f32 "
                 "{%0,%1,%2,%3}, {%4,%5,%6,%7}, {%8,%9}, {%0,%1,%2,%3};"
                 : "+f"(d[0]), "+f"(d[1]), "+f"(d[2]), "+f"(d[3])
                 : "r"(a[0]), "r"(a[1]), "r"(a[2]), "r"(a[3]), "r"(b0), "r"(b1));
}
__device__ __forceinline__ void cpa16(float* s, const float* g) {
    unsigned sa = (unsigned)__cvta_generic_to_shared(s);
    asm volatile("cp.async.cg.shared.global [%0], [%1], 16;" :: "r"(sa), "l"(g));
}
#define CP_COMMIT() asm volatile("cp.async.commit_group;")
template <int N> __device__ __forceinline__ void cp_wait() {
    asm volatile("cp.async.wait_group %0;" :: "n"(N));
}
#define U(x) __float_as_uint(x)

__global__ __launch_bounds__(NT, 4) void fa_tf32_kernel(
    const float* __restrict__ gq, const float* __restrict__ gk, const float* __restrict__ gv,
    const float* __restrict__ eq, const float* __restrict__ ek, const float* __restrict__ ev,
    float* __restrict__ gout)
{
    extern __shared__ float sm[];
    float* QP = sm + SM_QP;     // Q in prologue, P in mainloop
    float* Ks = sm + SM_K;
    float* Vs = sm + SM_V;

    const int h  = blockIdx.y;
    const int bx = blockIdx.x;
    int u = 0;
    #pragma unroll
    for (int i = 1; i < 8; i++) u += (bx >= c_qstart[i]);
    const int seqlen = c_seqlen[u];
    const int q0     = (bx - c_qstart[u]) * 64;
    const int b      = c_batch[u];
    const int soff   = c_soff[u];
    const int obase  = c_obase[u];

    const int tid  = threadIdx.x;
    const int lane = tid & 31;
    const int gID  = lane >> 2;   // 0..7
    const int t4   = lane & 3;    // 0..3
    const int m0   = (tid >> 5) * 16;   // warp's local q-row base

    // loader mapping for K/V tiles: each thread covers rows lrow, +16, +32, +48
    const int lrow = tid >> 3;          // 0..15
    const int lc4  = (tid & 7) * 2;     // float4 columns lc4, lc4+1

    // ---- Q load: scale by 0.125*log2e, cvt to tf32, store to smem ----
    #pragma unroll
    for (int it = 0; it < 8; it++) {
        int idx = tid + NT * it;           // 0..1023 = 64 rows x 16 float4
        int row = idx >> 4, c4 = idx & 15;
        int rg  = q0 + row;                // < ceil64(seqlen) <= lc: valid memory
        const float* src = (rg < 128)
            ? (eq + (((b * 128  + rg            ) * 16 + h) * 64) + 4 * c4)
            : (gq + (((b * 1536 + soff + rg - 128) * 16 + h) * 64) + 4 * c4);
        float4 v = *(const float4*)src;
        uint4 o;
        o.x = f2tf(v.x * QKSCALE); o.y = f2tf(v.y * QKSCALE);
        o.z = f2tf(v.z * QKSCALE); o.w = f2tf(v.w * QKSCALE);
        *(uint4*)(QP + row * QS_STRIDE + 4 * c4) = o;
    }

    const int ktiles = (seqlen + 63) >> 6;

    // ---- prologue: issue K(0) ----
    #pragma unroll
    for (int it = 0; it < 8; it++) {
        int idx = tid + NT * it;
        int row = idx >> 4, c4 = idx & 15;
        const float* sk = (row < 128)
            ? (ek + (((b * 128  + row ) * 16 + h) * 64) + 4 * c4)
            : (gk + (((b * 1536 + soff + row - 128) * 16 + h) * 64) + 4 * c4);
        cpa16(Ks + row * KS_STRIDE + 4 * c4, sk);
    }
    CP_COMMIT();

    __syncthreads();   // Qs visible to all warps

    // ---- Q fragments (persistent) ----
    unsigned qf[8][4];
    #pragma unroll
    for (int kc = 0; kc < 8; kc++) {
        qf[kc][0] = U(QP[(m0 + gID    ) * QS_STRIDE + kc * 8 + t4    ]);
        qf[kc][1] = U(QP[(m0 + gID + 8) * QS_STRIDE + kc * 8 + t4    ]);
        qf[kc][2] = U(QP[(m0 + gID    ) * QS_STRIDE + kc * 8 + t4 + 4]);
        qf[kc][3] = U(QP[(m0 + gID + 8) * QS_STRIDE + kc * 8 + t4 + 4]);
    }
    __syncwarp();      // all lanes' Q reads done before this warp's P overwrites

    float mA = -1e30f, mB = -1e30f, lA = 0.f, lB = 0.f;
    float oacc[8][4];
    #pragma unroll
    for (int nc = 0; nc < 8; nc++)
        #pragma unroll
        for (int j = 0; j < 4; j++) oacc[nc][j] = 0.f;

    for (int kt = 0; kt < ktiles; kt++) {
        const bool havenext = (kt + 1 < ktiles);

        // ---- A: K(kt) complete (everything older too), publish ----
        cp_wait<0>();
        __syncthreads();   // K(kt) visible; all PV(kt-1) V readers done

        // ---- issue V(kt) (buffer idle since barrier A); covered by S+softmax ----
        {
            const int k0 = kt * 64;
            #pragma unroll
            for (int it = 0; it < 8; it++) {
                int idx = tid + NT * it;
                int row = idx >> 4, c4 = idx & 15;
                int rg  = k0 + row;
                const float* sv = (rg < 128)
                    ? (ev + (((b * 128  + rg            ) * 16 + h) * 64) + 4 * c4)
                    : (gv + (((b * 1536 + soff + rg - 128) * 16 + h) * 64) + 4 * c4);
                cpa16(Vs + row * VS_STRIDE + 4 * c4, sv);
            }
            CP_COMMIT();
        }

        // ---- S = Q K^T : 8 n-chunks x 8 k-chunks of m16n8k8 ----
        float sacc[8][4];
        #pragma unroll
        for (int nc = 0; nc < 8; nc++) {
            sacc[nc][0] = 0.f; sacc[nc][1] = 0.f; sacc[nc][2] = 0.f; sacc[nc][3] = 0.f;
            #pragma unroll
            for (int kc = 0; kc < 8; kc++) {
                unsigned b0 = U(Ks[(nc * 8 + gID) * KS_STRIDE + kc * 8 + t4    ]);
                unsigned b1 = U(Ks[(nc * 8 + gID) * KS_STRIDE + kc * 8 + t4 + 4]);
                mma8(sacc[nc], qf[kc], b0, b1);
            }
        }

        __syncthreads();   // B: all S reads of K(kt) done

        // ---- issue K(kt+1) into the single K buffer; covered by softmax+PV ----
        if (havenext) {
            const int k0n = (kt + 1) * 64;
            #pragma unroll
            for (int it = 0; it < 8; it++) {
                int idx = tid + NT * it;
                int row = idx >> 4, c4 = idx & 15;
                int rg  = k0n + row;
                const float* sk = (rg < 128)
                    ? (ek + (((b * 128  + rg            ) * 16 + h) * 64) + 4 * c4)
                    : (gk + (((b * 1536 + soff + rg - 128) * 16 + h) * 64) + 4 * c4);
                cpa16(Ks + row * KS_STRIDE + 4 * c4, sk);
            }
            CP_COMMIT();
        }

        // ---- key-validity mask ----
        const int kbase = kt * 64;
        #pragma unroll
        for (int nc = 0; nc < 8; nc++) {
            int col0 = kbase + nc * 8 + 2 * t4;
            if (col0     >= seqlen) { sacc[nc][0] = -1e30f; sacc[nc][2] = -1e30f; }
            if (col0 + 1 >= seqlen) { sacc[nc][1] = -1e30f; sacc[nc][3] = -1e30f; }
        }

        // ---- online softmax (rows gID / gID+8; stats over 4 t4-lanes) ----
        float rmA = -1e30f, rmB = -1e30f;
        #pragma unroll
        for (int nc = 0; nc < 8; nc++) {
            rmA = fmaxf(rmA, fmaxf(sacc[nc][0], sacc[nc][1]));
            rmB = fmaxf(rmB, fmaxf(sacc[nc][2], sacc[nc][3]));
        }
        rmA = fmaxf(rmA, __shfl_xor_sync(0xffffffffu, rmA, 1));
        rmA = fmaxf(rmA, __shfl_xor_sync(0xffffffffu, rmA, 2));
        rmB = fmaxf(rmB, __shfl_xor_sync(0xffffffffu, rmB, 1));
        rmB = fmaxf(rmB, __shfl_xor_sync(0xffffffffu, rmB, 2));

        const float nmA = fmaxf(mA, rmA), nmB = fmaxf(mB, rmB);
        const float aA = ex2(mA - nmA), aB = ex2(mB - nmB);
        mA = nmA; mB = nmB;

        float sumA = 0.f, sumB = 0.f;
        #pragma unroll
        for (int nc = 0; nc < 8; nc++) {
            float p0 = ex2(sacc[nc][0] - nmA);
            float p1 = ex2(sacc[nc][1] - nmA);
            float p2 = ex2(sacc[nc][2] - nmB);
            float p3 = ex2(sacc[nc][3] - nmB);
            sumA += p0 + p1; sumB += p2 + p3;
            uint2 wA; wA.x = f2tf(p0); wA.y = f2tf(p1);
            uint2 wB; wB.x = f2tf(p2); wB.y = f2tf(p3);
            *(uint2*)(QP + (m0 + gID    ) * QS_STRIDE + nc * 8 + 2 * t4) = wA;
            *(uint2*)(QP + (m0 + gID + 8) * QS_STRIDE + nc * 8 + 2 * t4) = wB;
        }
        sumA += __shfl_xor_sync(0xffffffffu, sumA, 1);
        sumA += __shfl_xor_sync(0xffffffffu, sumA, 2);
        sumB += __shfl_xor_sync(0xffffffffu, sumB, 1);
        sumB += __shfl_xor_sync(0xffffffffu, sumB, 2);
        lA = lA * aA + sumA;
        lB = lB * aB + sumB;

        #pragma unroll
        for (int nc = 0; nc < 8; nc++) {
            oacc[nc][0] *= aA; oacc[nc][1] *= aA;
            oacc[nc][2] *= aB; oacc[nc][3] *= aB;
        }

        // ---- C: V(kt) complete (K(kt+1) may remain in flight), publish ----
        if (havenext) cp_wait<1>(); else cp_wait<0>();
        __syncthreads();

        // ---- O += P V : k over keys (8 chunks), n over d (8 chunks) ----
        #pragma unroll
        for (int kc = 0; kc < 8; kc++) {
            unsigned a[4];
            a[0] = U(QP[(m0 + gID    ) * QS_STRIDE + kc * 8 + t4    ]);
            a[1] = U(QP[(m0 + gID + 8) * QS_STRIDE + kc * 8 + t4    ]);
            a[2] = U(QP[(m0 + gID    ) * QS_STRIDE + kc * 8 + t4 + 4]);
            a[3] = U(QP[(m0 + gID + 8) * QS_STRIDE + kc * 8 + t4 + 4]);
            #pragma unroll
            for (int nc = 0; nc < 8; nc++) {
                unsigned b0 = U(Vs[(kc * 8 + t4    ) * VS_STRIDE + nc * 8 + gID]);
                unsigned b1 = U(Vs[(kc * 8 + t4 + 4) * VS_STRIDE + nc * 8 + gID]);
                mma8(oacc[nc], a, b0, b1);
            }
        }
        // next iteration's barrier A protects Vs overwrite
    }

    // ---- epilogue: normalize + packed store ----
    const float invA = 1.f / lA, invB = 1.f / lB;
    const int qrA = q0 + m0 + gID;
    const int qrB = qrA + 8;
    #pragma unroll
    for (int nc = 0; nc < 8; nc++) {
        const int col = nc * 8 + 2 * t4;
        if (qrA < seqlen) {
            float2 v; v.x = oacc[nc][0] * invA; v.y = oacc[nc][1] * invA;
            *(float2*)(gout + (((long)(obase + qrA)) * 16 + h) * 64 + col) = v;
        }
        if (qrB < seqlen) {
            float2 v; v.x = oacc[nc][2] * invB; v.y = oacc[nc][3] * invB;
            *(float2*)(gout + (((long)(obase + qrB)) * 16 + h) * 64 + col) = v;
        }
    }
}

extern "C" void kernel_launch(void* const* d_in, const int* in_sizes, int n_in,
                              void* d_out, int out_size)
{
    const float* gq = (const float*)d_in[0];
    const float* gk = (const float*)d_in[1];
    const float* gv = (const float*)d_in[2];
    const float* eq = (const float*)d_in[3];
    const float* ek = (const float*)d_in[4];
    const float* ev = (const float*)d_in[5];
    float* out = (float*)d_out;

    const size_t smem_bytes = SM_TOTAL_FLOATS * sizeof(float);   // 53248 B
    cudaFuncSetAttribute(fa_tf32_kernel,
                         cudaFuncAttributeMaxDynamicSharedMemorySize,
                         (int)smem_bytes);

    dim3 grid(94, 16, 1);   // 94 q-tiles (BQ=64) x 16 heads
    fa_tf32_kernel<<<grid, NT, smem_bytes>>>(gq, gk, gv, eq, ek, ev, out);
}